// round 3
// baseline (speedup 1.0000x reference)
#include <cuda_runtime.h>
#include <cstdint>

#define HD    256
#define OUTD  64
#define BSZ   64
#define NP    64
#define TT    128
#define MROWS (BSZ*NP)
#define M_U   (TT*BSZ)

__device__ float g_x[MROWS*HD];
__device__ float g_h[MROWS*HD];
__device__ float g_a[MROWS*HD];
__device__ float g_uproj[M_U*HD];   // u@W_ih^T + b_ih   (b_hh added later, matching ref association)
__device__ float g_lp[MROWS];
__device__ uint2 g_keys[257];
__device__ float g_logdet;

// ---------------- Threefry-2x32 (JAX partitionable convention) ----------------
__device__ __forceinline__ void tf_block(uint32_t k0, uint32_t k1,
                                         uint32_t x0, uint32_t x1,
                                         uint32_t &o0, uint32_t &o1) {
    uint32_t ks2 = k0 ^ k1 ^ 0x1BD11BDAu;
    x0 += k0; x1 += k1;
#define TFR(r) { x0 += x1; x1 = (x1 << (r)) | (x1 >> (32 - (r))); x1 ^= x0; }
    TFR(13) TFR(15) TFR(26) TFR(6)
    x0 += k1;  x1 += ks2 + 1u;
    TFR(17) TFR(29) TFR(16) TFR(24)
    x0 += ks2; x1 += k0 + 2u;
    TFR(13) TFR(15) TFR(26) TFR(6)
    x0 += k0;  x1 += k1 + 3u;
    TFR(17) TFR(29) TFR(16) TFR(24)
    x0 += k1;  x1 += ks2 + 4u;
    TFR(13) TFR(15) TFR(26) TFR(6)
    x0 += ks2; x1 += k0 + 5u;
#undef TFR
    o0 = x0; o1 = x1;
}

__device__ __forceinline__ uint32_t tf_bits(uint2 k, uint32_t i) {
    uint32_t a, b;
    tf_block(k.x, k.y, 0u, i, a, b);
    return a ^ b;
}

// ---------------- XLA-matched elementwise ops ----------------
__device__ __forceinline__ float xla_erfinv(float x) {
    float w = -log1pf(-x * x);
    float p;
    if (w < 5.0f) {
        w = w - 2.5f;
        p = 2.81022636e-08f;
        p = fmaf(p, w, 3.43273939e-07f);
        p = fmaf(p, w, -3.5233877e-06f);
        p = fmaf(p, w, -4.39150654e-06f);
        p = fmaf(p, w, 0.00021858087f);
        p = fmaf(p, w, -0.00125372503f);
        p = fmaf(p, w, -0.00417768164f);
        p = fmaf(p, w, 0.246640727f);
        p = fmaf(p, w, 1.50140941f);
    } else {
        w = sqrtf(w) - 3.0f;
        p = -0.000200214257f;
        p = fmaf(p, w, 0.000100950558f);
        p = fmaf(p, w, 0.00134934322f);
        p = fmaf(p, w, -0.00367342844f);
        p = fmaf(p, w, 0.00573950773f);
        p = fmaf(p, w, -0.0076224613f);
        p = fmaf(p, w, 0.00943887047f);
        p = fmaf(p, w, 1.00167406f);
        p = fmaf(p, w, 2.83297682f);
    }
    return p * x;
}

__device__ __forceinline__ float bits_to_normal(uint32_t bits) {
    const float lo = -0.99999994f;
    float f = __uint_as_float((bits >> 9) | 0x3f800000u) - 1.0f;
    float u = __fadd_rn(__fmul_rn(f, 2.0f), lo);   // mul by 2 exact; matches ref either way
    u = fmaxf(lo, u);
    return 1.4142135623730951f * xla_erfinv(u);
}

__device__ __forceinline__ float bits_to_gumbel(uint32_t bits) {
    const float tiny = 1.17549435e-38f;
    float f = __uint_as_float((bits >> 9) | 0x3f800000u) - 1.0f;
    float u = fmaxf(tiny, __fadd_rn(f, tiny));
    return -logf(-logf(u));
}

__device__ __forceinline__ float xla_tanh(float x) {
    if (fabsf(x) < 0.0004f) return x;
    float xc = fminf(fmaxf(x, -7.90531110763549805f), 7.90531110763549805f);
    float x2 = __fmul_rn(xc, xc);
    float p = -2.76076847742355e-16f;
    p = fmaf(p, x2, 2.00018790482477e-13f);
    p = fmaf(p, x2, -8.60467152213735e-11f);
    p = fmaf(p, x2, 5.12229709037114e-08f);
    p = fmaf(p, x2, 1.48572235717979e-05f);
    p = fmaf(p, x2, 6.37261928875436e-04f);
    p = fmaf(p, x2, 4.89352455891786e-03f);
    p = __fmul_rn(p, xc);
    float q = 1.19825839466702e-06f;
    q = fmaf(q, x2, 1.18534705686654e-04f);
    q = fmaf(q, x2, 2.26843463243900e-03f);
    q = fmaf(q, x2, 4.89352518554385e-03f);
    return __fdiv_rn(p, q);
}

// ---------------- Prologue ----------------
__global__ __launch_bounds__(256) void k_keys(const float* __restrict__ sy) {
    int j = threadIdx.x;
    uint32_t a0, a1;
    tf_block(0u, 42u, 0u, 1u, a0, a1);           // keyA = fold_in(key(42), 1)
    uint32_t s0, s1;
    tf_block(a0, a1, 0u, (uint32_t)j, s0, s1);   // split(keyA, 256)[j]
    g_keys[1 + j] = make_uint2(s0, s1);
    if (j == 0) {
        uint32_t b0, b1;
        tf_block(0u, 42u, 0u, 0u, b0, b1);       // fold_in(key(42), 0)
        g_keys[0] = make_uint2(b0, b1);
        float s = 0.0f;
        for (int o = 0; o < OUTD; o++) s += logf(sy[o]);
        g_logdet = 0.5f * s + 32.0f * 1.8378770664093453f;  // common shift; argmax-invariant
    }
}

__global__ __launch_bounds__(256) void k_x0() {
    uint32_t i = blockIdx.x * 256u + threadIdx.x;
    uint2 key = g_keys[0];
    g_x[i] = bits_to_normal(tf_bits(key, i));
}

// uproj = u @ W_ih^T + b_ih   (NT GEMM, M=8192)
__global__ __launch_bounds__(256) void k_uproj(const float* __restrict__ u,
                                               const float* __restrict__ Wih,
                                               const float* __restrict__ bih) {
    __shared__ float As[64][17];
    __shared__ float Bs[64][17];
    int tid = threadIdx.x, tx = tid & 15, ty = tid >> 4;
    int row0 = blockIdx.x * 64, col0 = blockIdx.y * 64;
    int lr = tid >> 2, lc = (tid & 3) * 4;
    float acc[4][4] = {};
    for (int k0 = 0; k0 < HD; k0 += 16) {
        float4 av = *(const float4*)&u[(size_t)(row0 + lr) * HD + k0 + lc];
        As[lr][lc] = av.x; As[lr][lc+1] = av.y; As[lr][lc+2] = av.z; As[lr][lc+3] = av.w;
        float4 bv = *(const float4*)&Wih[(size_t)(col0 + lr) * HD + k0 + lc];
        Bs[lr][lc] = bv.x; Bs[lr][lc+1] = bv.y; Bs[lr][lc+2] = bv.z; Bs[lr][lc+3] = bv.w;
        __syncthreads();
#pragma unroll
        for (int kk = 0; kk < 16; kk++) {
            float a[4], b[4];
#pragma unroll
            for (int i = 0; i < 4; i++) a[i] = As[ty*4 + i][kk];
#pragma unroll
            for (int j = 0; j < 4; j++) b[j] = Bs[tx*4 + j][kk];
#pragma unroll
            for (int i = 0; i < 4; i++)
#pragma unroll
                for (int j = 0; j < 4; j++)
                    acc[i][j] = fmaf(a[i], b[j], acc[i][j]);
        }
        __syncthreads();
    }
#pragma unroll
    for (int i = 0; i < 4; i++) {
        int r = row0 + ty*4 + i;
#pragma unroll
        for (int j = 0; j < 4; j++) {
            int c = col0 + tx*4 + j;
            g_uproj[(size_t)r * HD + c] = __fadd_rn(acc[i][j], bih[c]);
        }
    }
}

// ---------------- Per-step kernels ----------------
// h = tanh(((uWih+bih) + xWhh) + bhh) + normal * sqrt(sx)   — ref association order
__global__ __launch_bounds__(256) void k_rnn(const float* __restrict__ Whh,
                                             const float* __restrict__ bhh,
                                             const float* __restrict__ sx,
                                             int t) {
    __shared__ float As[64][17];
    __shared__ float Bs[64][17];
    int tid = threadIdx.x, tx = tid & 15, ty = tid >> 4;
    int row0 = blockIdx.x * 64, col0 = blockIdx.y * 64;
    int lr = tid >> 2, lc = (tid & 3) * 4;
    float acc[4][4] = {};
    for (int k0 = 0; k0 < HD; k0 += 16) {
        float4 av = *(const float4*)&g_x[(size_t)(row0 + lr) * HD + k0 + lc];
        As[lr][lc] = av.x; As[lr][lc+1] = av.y; As[lr][lc+2] = av.z; As[lr][lc+3] = av.w;
        float4 bv = *(const float4*)&Whh[(size_t)(col0 + lr) * HD + k0 + lc];
        Bs[lr][lc] = bv.x; Bs[lr][lc+1] = bv.y; Bs[lr][lc+2] = bv.z; Bs[lr][lc+3] = bv.w;
        __syncthreads();
#pragma unroll
        for (int kk = 0; kk < 16; kk++) {
            float a[4], b[4];
#pragma unroll
            for (int i = 0; i < 4; i++) a[i] = As[ty*4 + i][kk];
#pragma unroll
            for (int j = 0; j < 4; j++) b[j] = Bs[tx*4 + j][kk];
#pragma unroll
            for (int i = 0; i < 4; i++)
#pragma unroll
                for (int j = 0; j < 4; j++)
                    acc[i][j] = fmaf(a[i], b[j], acc[i][j]);
        }
        __syncthreads();
    }
    uint2 nkey = g_keys[1 + 2*t];
#pragma unroll
    for (int i = 0; i < 4; i++) {
        int r = row0 + ty*4 + i;
        int b = r >> 6;
#pragma unroll
        for (int j = 0; j < 4; j++) {
            int c = col0 + tx*4 + j;
            float pre = __fadd_rn(__fadd_rn(g_uproj[(size_t)(t * BSZ + b) * HD + c],
                                            acc[i][j]),
                                  bhh[c]);
            float v = xla_tanh(pre);
            uint32_t idx = (uint32_t)r * HD + (uint32_t)c;
            float nz = __fmul_rn(bits_to_normal(tf_bits(nkey, idx)), sqrtf(sx[c]));
            g_h[(size_t)r * HD + c] = __fadd_rn(v, nz);
        }
    }
}

// a = relu(h@W1 + b1)   (NN GEMM)
__global__ __launch_bounds__(256) void k_ffn1(const float* __restrict__ W1,
                                              const float* __restrict__ b1) {
    __shared__ float As[64][17];
    __shared__ float Bs[16][68];
    int tid = threadIdx.x, tx = tid & 15, ty = tid >> 4;
    int row0 = blockIdx.x * 64, col0 = blockIdx.y * 64;
    int lr = tid >> 2, lc = (tid & 3) * 4;
    int lr2 = tid >> 4, lc2 = (tid & 15) * 4;
    float acc[4][4] = {};
    for (int k0 = 0; k0 < HD; k0 += 16) {
        float4 av = *(const float4*)&g_h[(size_t)(row0 + lr) * HD + k0 + lc];
        As[lr][lc] = av.x; As[lr][lc+1] = av.y; As[lr][lc+2] = av.z; As[lr][lc+3] = av.w;
        float4 bv = *(const float4*)&W1[(size_t)(k0 + lr2) * HD + col0 + lc2];
        Bs[lr2][lc2] = bv.x; Bs[lr2][lc2+1] = bv.y; Bs[lr2][lc2+2] = bv.z; Bs[lr2][lc2+3] = bv.w;
        __syncthreads();
#pragma unroll
        for (int kk = 0; kk < 16; kk++) {
            float a[4], b[4];
#pragma unroll
            for (int i = 0; i < 4; i++) a[i] = As[ty*4 + i][kk];
#pragma unroll
            for (int j = 0; j < 4; j++) b[j] = Bs[kk][tx*4 + j];
#pragma unroll
            for (int i = 0; i < 4; i++)
#pragma unroll
                for (int j = 0; j < 4; j++)
                    acc[i][j] = fmaf(a[i], b[j], acc[i][j]);
        }
        __syncthreads();
    }
#pragma unroll
    for (int i = 0; i < 4; i++) {
        int r = row0 + ty*4 + i;
#pragma unroll
        for (int j = 0; j < 4; j++) {
            int c = col0 + tx*4 + j;
            g_a[(size_t)r * HD + c] = fmaxf(__fadd_rn(acc[i][j], b1[c]), 0.0f);
        }
    }
}

// y_hat = a@W2 + b2; store to out; lp via XLA-GPU row-reduce tree:
// lane partial = term[lane] + term[lane+32], then shfl.down 16,8,4,2,1.
__global__ __launch_bounds__(256) void k_ffn2(const float* __restrict__ W2,
                                              const float* __restrict__ b2,
                                              const float* __restrict__ y,
                                              const float* __restrict__ sy,
                                              float* __restrict__ out,
                                              int t) {
    int tid = threadIdx.x;
    int warp = tid >> 5, lane = tid & 31;
    int wglobal = blockIdx.x * 8 + warp;           // 64 blocks * 8 warps = 512 warps
    float w_b0 = b2[lane],       w_b1 = b2[lane + 32];
    float w_s0 = sy[lane],       w_s1 = sy[lane + 32];
    float logdet = g_logdet;
    for (int r = wglobal; r < MROWS; r += 512) {
        const float* arow = &g_a[(size_t)r * HD];
        float acc0 = 0.0f, acc1 = 0.0f;
#pragma unroll 8
        for (int k = 0; k < HD; k++) {
            float av = __ldg(&arow[k]);
            acc0 = fmaf(av, __ldg(&W2[(size_t)k * OUTD + lane]), acc0);
            acc1 = fmaf(av, __ldg(&W2[(size_t)k * OUTD + lane + 32]), acc1);
        }
        float v0 = __fadd_rn(acc0, w_b0);
        float v1 = __fadd_rn(acc1, w_b1);
        size_t obase = (size_t)t * (MROWS*OUTD) + (size_t)r * OUTD;
        out[obase + lane]      = v0;
        out[obase + lane + 32] = v1;
        int b = r >> 6;
        const float* yrow = &y[(size_t)(t * BSZ + b) * OUTD];
        float d0 = __fsub_rn(v0, yrow[lane]);
        float d1 = __fsub_rn(v1, yrow[lane + 32]);
        float t0 = __fdiv_rn(__fmul_rn(d0, d0), w_s0);
        float t1 = __fdiv_rn(__fmul_rn(d1, d1), w_s1);
        float s = __fadd_rn(t0, t1);               // strided pair, first-then-second
#pragma unroll
        for (int off = 16; off >= 1; off >>= 1)
            s = __fadd_rn(s, __shfl_down_sync(0xffffffffu, s, off));
        if (lane == 0)
            g_lp[r] = __fsub_rn(__fmul_rn(-0.5f, s), logdet);
    }
}

// log_softmax (XLA tree) + gumbel-argmax resample + particle gather. One block per batch.
__global__ __launch_bounds__(256) void k_resample(int t) {
    __shared__ float logw_s[64];
    __shared__ int   idx_s[64];
    int tid = threadIdx.x;
    int b = blockIdx.x;
    if (tid < 32) {
        float v0 = g_lp[b*64 + tid];
        float v1 = g_lp[b*64 + 32 + tid];
        float m = fmaxf(v0, v1);
#pragma unroll
        for (int off = 16; off >= 1; off >>= 1)
            m = fmaxf(m, __shfl_xor_sync(0xffffffffu, m, off));
        float sh0 = __fsub_rn(v0, m);
        float sh1 = __fsub_rn(v1, m);
        // XLA row-reduce tree for sum(exp(shifted))
        float e = __fadd_rn(expf(sh0), expf(sh1));
#pragma unroll
        for (int off = 16; off >= 1; off >>= 1)
            e = __fadd_rn(e, __shfl_down_sync(0xffffffffu, e, off));
        float ls = logf(__shfl_sync(0xffffffffu, e, 0));
        logw_s[tid]      = __fsub_rn(sh0, ls);
        logw_s[tid + 32] = __fsub_rn(sh1, ls);
    }
    __syncthreads();
    uint2 gkey = g_keys[1 + 2*t + 1];
    int w = tid >> 5, lane = tid & 31;
    for (int s = w; s < 64; s += 8) {
        uint32_t base = (uint32_t)s * 4096u + (uint32_t)b * 64u;
        float v0 = __fadd_rn(bits_to_gumbel(tf_bits(gkey, base + lane)),      logw_s[lane]);
        float v1 = __fadd_rn(bits_to_gumbel(tf_bits(gkey, base + 32 + lane)), logw_s[lane + 32]);
        float bv; int bi;
        if (v1 > v0) { bv = v1; bi = lane + 32; } else { bv = v0; bi = lane; }
#pragma unroll
        for (int off = 16; off >= 1; off >>= 1) {
            float ov = __shfl_xor_sync(0xffffffffu, bv, off);
            int   oi = __shfl_xor_sync(0xffffffffu, bi, off);
            if (ov > bv || (ov == bv && oi < bi)) { bv = ov; bi = oi; }
        }
        if (lane == 0) idx_s[s] = bi;
    }
    __syncthreads();
    const float4* hsrc = (const float4*)g_h;
    float4* xdst = (float4*)g_x;
    for (int e = tid; e < 64*64; e += 256) {
        int s = e >> 6, c4 = e & 63;
        xdst[(size_t)(b*64 + s) * 64 + c4] = hsrc[(size_t)(b*64 + idx_s[s]) * 64 + c4];
    }
}

extern "C" void kernel_launch(void* const* d_in, const int* in_sizes, int n_in,
                              void* d_out, int out_size) {
    (void)in_sizes; (void)n_in; (void)out_size;
    const float* u   = (const float*)d_in[0];
    const float* y   = (const float*)d_in[1];
    const float* Wih = (const float*)d_in[2];
    const float* Whh = (const float*)d_in[3];
    const float* bih = (const float*)d_in[4];
    const float* bhh = (const float*)d_in[5];
    const float* W1  = (const float*)d_in[6];
    const float* b1  = (const float*)d_in[7];
    const float* W2  = (const float*)d_in[8];
    const float* b2  = (const float*)d_in[9];
    const float* sx  = (const float*)d_in[10];
    const float* sy  = (const float*)d_in[11];
    float* out = (float*)d_out;

    k_keys<<<1, 256>>>(sy);
    k_x0<<<4096, 256>>>();
    k_uproj<<<dim3(128, 4), 256>>>(u, Wih, bih);
    for (int t = 0; t < TT; t++) {
        k_rnn<<<dim3(64, 4), 256>>>(Whh, bhh, sx, t);
        k_ffn1<<<dim3(64, 4), 256>>>(W1, b1);
        k_ffn2<<<64, 256>>>(W2, b2, y, sy, out, t);
        k_resample<<<64, 256>>>(t);
    }
}

// round 4
// speedup vs baseline: 2.2341x; 2.2341x over previous
#include <cuda_runtime.h>
#include <cstdint>

#define HD    256
#define OUTD  64
#define BSZ   64
#define NP    64
#define TT    128
#define MROWS (BSZ*NP)
#define M_U   (TT*BSZ)

__device__ float g_x[MROWS*HD];
__device__ float g_h[MROWS*HD];
__device__ float g_a[MROWS*HD];
__device__ float g_uproj[M_U*HD];   // u@W_ih^T + b_ih
__device__ uint2 g_keys[257];
__device__ float g_logdet;

// ---------------- Threefry-2x32 (JAX partitionable convention) ----------------
__device__ __forceinline__ void tf_block(uint32_t k0, uint32_t k1,
                                         uint32_t x0, uint32_t x1,
                                         uint32_t &o0, uint32_t &o1) {
    uint32_t ks2 = k0 ^ k1 ^ 0x1BD11BDAu;
    x0 += k0; x1 += k1;
#define TFR(r) { x0 += x1; x1 = (x1 << (r)) | (x1 >> (32 - (r))); x1 ^= x0; }
    TFR(13) TFR(15) TFR(26) TFR(6)
    x0 += k1;  x1 += ks2 + 1u;
    TFR(17) TFR(29) TFR(16) TFR(24)
    x0 += ks2; x1 += k0 + 2u;
    TFR(13) TFR(15) TFR(26) TFR(6)
    x0 += k0;  x1 += k1 + 3u;
    TFR(17) TFR(29) TFR(16) TFR(24)
    x0 += k1;  x1 += ks2 + 4u;
    TFR(13) TFR(15) TFR(26) TFR(6)
    x0 += ks2; x1 += k0 + 5u;
#undef TFR
    o0 = x0; o1 = x1;
}

__device__ __forceinline__ uint32_t tf_bits(uint2 k, uint32_t i) {
    uint32_t a, b;
    tf_block(k.x, k.y, 0u, i, a, b);
    return a ^ b;
}

// ---------------- XLA-matched elementwise ops ----------------
__device__ __forceinline__ float xla_erfinv(float x) {
    float w = -log1pf(-x * x);
    float p;
    if (w < 5.0f) {
        w = w - 2.5f;
        p = 2.81022636e-08f;
        p = fmaf(p, w, 3.43273939e-07f);
        p = fmaf(p, w, -3.5233877e-06f);
        p = fmaf(p, w, -4.39150654e-06f);
        p = fmaf(p, w, 0.00021858087f);
        p = fmaf(p, w, -0.00125372503f);
        p = fmaf(p, w, -0.00417768164f);
        p = fmaf(p, w, 0.246640727f);
        p = fmaf(p, w, 1.50140941f);
    } else {
        w = sqrtf(w) - 3.0f;
        p = -0.000200214257f;
        p = fmaf(p, w, 0.000100950558f);
        p = fmaf(p, w, 0.00134934322f);
        p = fmaf(p, w, -0.00367342844f);
        p = fmaf(p, w, 0.00573950773f);
        p = fmaf(p, w, -0.0076224613f);
        p = fmaf(p, w, 0.00943887047f);
        p = fmaf(p, w, 1.00167406f);
        p = fmaf(p, w, 2.83297682f);
    }
    return p * x;
}

__device__ __forceinline__ float bits_to_normal(uint32_t bits) {
    const float lo = -0.99999994f;
    float f = __uint_as_float((bits >> 9) | 0x3f800000u) - 1.0f;
    float u = __fadd_rn(__fmul_rn(f, 2.0f), lo);
    u = fmaxf(lo, u);
    return 1.4142135623730951f * xla_erfinv(u);
}

__device__ __forceinline__ float bits_to_gumbel(uint32_t bits) {
    const float tiny = 1.17549435e-38f;
    float f = __uint_as_float((bits >> 9) | 0x3f800000u) - 1.0f;
    float u = fmaxf(tiny, __fadd_rn(f, tiny));
    return -logf(-logf(u));
}

__device__ __forceinline__ float xla_tanh(float x) {
    if (fabsf(x) < 0.0004f) return x;
    float xc = fminf(fmaxf(x, -7.90531110763549805f), 7.90531110763549805f);
    float x2 = __fmul_rn(xc, xc);
    float p = -2.76076847742355e-16f;
    p = fmaf(p, x2, 2.00018790482477e-13f);
    p = fmaf(p, x2, -8.60467152213735e-11f);
    p = fmaf(p, x2, 5.12229709037114e-08f);
    p = fmaf(p, x2, 1.48572235717979e-05f);
    p = fmaf(p, x2, 6.37261928875436e-04f);
    p = fmaf(p, x2, 4.89352455891786e-03f);
    p = __fmul_rn(p, xc);
    float q = 1.19825839466702e-06f;
    q = fmaf(q, x2, 1.18534705686654e-04f);
    q = fmaf(q, x2, 2.26843463243900e-03f);
    q = fmaf(q, x2, 4.89352518554385e-03f);
    return __fdiv_rn(p, q);
}

// ---------------- Prologue ----------------
__global__ __launch_bounds__(256) void k_keys(const float* __restrict__ sy) {
    int j = threadIdx.x;
    uint32_t a0, a1;
    tf_block(0u, 42u, 0u, 1u, a0, a1);           // keyA = fold_in(key(42), 1)
    uint32_t s0, s1;
    tf_block(a0, a1, 0u, (uint32_t)j, s0, s1);   // split(keyA, 256)[j]
    g_keys[1 + j] = make_uint2(s0, s1);
    if (j == 0) {
        uint32_t b0, b1;
        tf_block(0u, 42u, 0u, 0u, b0, b1);       // fold_in(key(42), 0)
        g_keys[0] = make_uint2(b0, b1);
        float s = 0.0f;
        for (int o = 0; o < OUTD; o++) s += logf(sy[o]);
        g_logdet = 0.5f * s + 32.0f * 1.8378770664093453f;
    }
}

__global__ __launch_bounds__(256) void k_x0() {
    uint32_t i = blockIdx.x * 256u + threadIdx.x;
    uint2 key = g_keys[0];
    g_x[i] = bits_to_normal(tf_bits(key, i));
}

// ------- NT GEMM core (K-major smem, float4 LDS, 2-stage prefetch) -------
// uproj = u @ W_ih^T + b_ih   (M=8192)
__global__ __launch_bounds__(256) void k_uproj(const float* __restrict__ u,
                                               const float* __restrict__ Wih,
                                               const float* __restrict__ bih) {
    __shared__ float As[16][68];
    __shared__ float Bs[16][68];
    int tid = threadIdx.x, tx = tid & 15, ty = tid >> 4;
    int row0 = blockIdx.x * 64, col0 = blockIdx.y * 64;
    int lr = tid >> 2, lc4 = (tid & 3) * 4;
    const float* Aptr = &u[(size_t)(row0 + lr) * HD + lc4];
    const float* Bptr = &Wih[(size_t)(col0 + lr) * HD + lc4];
    float4 a_reg = *(const float4*)Aptr;
    float4 b_reg = *(const float4*)Bptr;
    float acc[4][4] = {};
#pragma unroll 1
    for (int p = 0; p < 16; p++) {
        As[lc4+0][lr] = a_reg.x; As[lc4+1][lr] = a_reg.y;
        As[lc4+2][lr] = a_reg.z; As[lc4+3][lr] = a_reg.w;
        Bs[lc4+0][lr] = b_reg.x; Bs[lc4+1][lr] = b_reg.y;
        Bs[lc4+2][lr] = b_reg.z; Bs[lc4+3][lr] = b_reg.w;
        __syncthreads();
        if (p < 15) {
            a_reg = *(const float4*)(Aptr + (p + 1) * 16);
            b_reg = *(const float4*)(Bptr + (p + 1) * 16);
        }
#pragma unroll
        for (int kk = 0; kk < 16; kk++) {
            float4 a4 = *(const float4*)&As[kk][ty*4];
            float4 b4 = *(const float4*)&Bs[kk][tx*4];
            float a[4] = {a4.x, a4.y, a4.z, a4.w};
            float b[4] = {b4.x, b4.y, b4.z, b4.w};
#pragma unroll
            for (int i = 0; i < 4; i++)
#pragma unroll
                for (int j = 0; j < 4; j++)
                    acc[i][j] = fmaf(a[i], b[j], acc[i][j]);
        }
        __syncthreads();
    }
#pragma unroll
    for (int i = 0; i < 4; i++) {
        int r = row0 + ty*4 + i;
#pragma unroll
        for (int j = 0; j < 4; j++) {
            int c = col0 + tx*4 + j;
            g_uproj[(size_t)r * HD + c] = __fadd_rn(acc[i][j], bih[c]);
        }
    }
}

// h = tanh(((uWih+bih) + xWhh) + bhh) + normal * sqrt(sx)
__global__ __launch_bounds__(256) void k_rnn(const float* __restrict__ Whh,
                                             const float* __restrict__ bhh,
                                             const float* __restrict__ sx,
                                             int t) {
    __shared__ float As[16][68];
    __shared__ float Bs[16][68];
    int tid = threadIdx.x, tx = tid & 15, ty = tid >> 4;
    int row0 = blockIdx.x * 64, col0 = blockIdx.y * 64;
    int lr = tid >> 2, lc4 = (tid & 3) * 4;
    const float* Aptr = &g_x[(size_t)(row0 + lr) * HD + lc4];
    const float* Bptr = &Whh[(size_t)(col0 + lr) * HD + lc4];
    float4 a_reg = *(const float4*)Aptr;
    float4 b_reg = *(const float4*)Bptr;
    float acc[4][4] = {};
#pragma unroll 1
    for (int p = 0; p < 16; p++) {
        As[lc4+0][lr] = a_reg.x; As[lc4+1][lr] = a_reg.y;
        As[lc4+2][lr] = a_reg.z; As[lc4+3][lr] = a_reg.w;
        Bs[lc4+0][lr] = b_reg.x; Bs[lc4+1][lr] = b_reg.y;
        Bs[lc4+2][lr] = b_reg.z; Bs[lc4+3][lr] = b_reg.w;
        __syncthreads();
        if (p < 15) {
            a_reg = *(const float4*)(Aptr + (p + 1) * 16);
            b_reg = *(const float4*)(Bptr + (p + 1) * 16);
        }
#pragma unroll
        for (int kk = 0; kk < 16; kk++) {
            float4 a4 = *(const float4*)&As[kk][ty*4];
            float4 b4 = *(const float4*)&Bs[kk][tx*4];
            float a[4] = {a4.x, a4.y, a4.z, a4.w};
            float b[4] = {b4.x, b4.y, b4.z, b4.w};
#pragma unroll
            for (int i = 0; i < 4; i++)
#pragma unroll
                for (int j = 0; j < 4; j++)
                    acc[i][j] = fmaf(a[i], b[j], acc[i][j]);
        }
        __syncthreads();
    }
    uint2 nkey = g_keys[1 + 2*t];
#pragma unroll
    for (int i = 0; i < 4; i++) {
        int r = row0 + ty*4 + i;
        int b = r >> 6;
#pragma unroll
        for (int j = 0; j < 4; j++) {
            int c = col0 + tx*4 + j;
            float pre = __fadd_rn(__fadd_rn(g_uproj[(size_t)(t * BSZ + b) * HD + c],
                                            acc[i][j]),
                                  bhh[c]);
            float v = xla_tanh(pre);
            uint32_t idx = (uint32_t)r * HD + (uint32_t)c;
            float nz = __fmul_rn(bits_to_normal(tf_bits(nkey, idx)), sqrtf(sx[c]));
            g_h[(size_t)r * HD + c] = __fadd_rn(v, nz);
        }
    }
}

// a = relu(h@W1 + b1)   (NN: B already K-major in gmem)
__global__ __launch_bounds__(256) void k_ffn1(const float* __restrict__ W1,
                                              const float* __restrict__ b1) {
    __shared__ float As[16][68];
    __shared__ float Bs[16][68];
    int tid = threadIdx.x, tx = tid & 15, ty = tid >> 4;
    int row0 = blockIdx.x * 64, col0 = blockIdx.y * 64;
    int lr = tid >> 2, lc4 = (tid & 3) * 4;
    int lr2 = tid >> 4, lc2 = (tid & 15) * 4;
    const float* Aptr = &g_h[(size_t)(row0 + lr) * HD + lc4];
    const float* Bptr = &W1[(size_t)lr2 * HD + col0 + lc2];
    float4 a_reg = *(const float4*)Aptr;
    float4 b_reg = *(const float4*)Bptr;
    float acc[4][4] = {};
#pragma unroll 1
    for (int p = 0; p < 16; p++) {
        As[lc4+0][lr] = a_reg.x; As[lc4+1][lr] = a_reg.y;
        As[lc4+2][lr] = a_reg.z; As[lc4+3][lr] = a_reg.w;
        *(float4*)&Bs[lr2][lc2] = b_reg;
        __syncthreads();
        if (p < 15) {
            a_reg = *(const float4*)(Aptr + (p + 1) * 16);
            b_reg = *(const float4*)(Bptr + (size_t)(p + 1) * 16 * HD);
        }
#pragma unroll
        for (int kk = 0; kk < 16; kk++) {
            float4 a4 = *(const float4*)&As[kk][ty*4];
            float4 b4 = *(const float4*)&Bs[kk][tx*4];
            float a[4] = {a4.x, a4.y, a4.z, a4.w};
            float b[4] = {b4.x, b4.y, b4.z, b4.w};
#pragma unroll
            for (int i = 0; i < 4; i++)
#pragma unroll
                for (int j = 0; j < 4; j++)
                    acc[i][j] = fmaf(a[i], b[j], acc[i][j]);
        }
        __syncthreads();
    }
#pragma unroll
    for (int i = 0; i < 4; i++) {
        int r = row0 + ty*4 + i;
#pragma unroll
        for (int j = 0; j < 4; j++) {
            int c = col0 + tx*4 + j;
            g_a[(size_t)r * HD + c] = fmaxf(__fadd_rn(acc[i][j], b1[c]), 0.0f);
        }
    }
}

// Fused: yhat = a@W2 + b2 (one block = one batch's 64x64 tile) -> out + smem;
// then lp (XLA tree), log_softmax, gumbel-argmax, particle gather.
__global__ __launch_bounds__(256) void k_out_resample(
        const float* __restrict__ W2, const float* __restrict__ b2,
        const float* __restrict__ y,  const float* __restrict__ sy,
        float* __restrict__ out, int t) {
    __shared__ float As[16][68];
    __shared__ float Bs[16][68];
    __shared__ float sm_out[64][68];
    __shared__ float lp_s[64];
    __shared__ float logw_s[64];
    __shared__ int   idx_s[64];
    int tid = threadIdx.x, tx = tid & 15, ty = tid >> 4;
    int b = blockIdx.x;
    int row0 = b * 64;
    int lr = tid >> 2, lc4 = (tid & 3) * 4;
    int lr2 = tid >> 4, lc2 = (tid & 15) * 4;
    const float* Aptr = &g_a[(size_t)(row0 + lr) * HD + lc4];
    const float* Bptr = &W2[(size_t)lr2 * OUTD + lc2];
    float4 a_reg = *(const float4*)Aptr;
    float4 b_reg = *(const float4*)Bptr;
    float acc[4][4] = {};
#pragma unroll 1
    for (int p = 0; p < 16; p++) {
        As[lc4+0][lr] = a_reg.x; As[lc4+1][lr] = a_reg.y;
        As[lc4+2][lr] = a_reg.z; As[lc4+3][lr] = a_reg.w;
        *(float4*)&Bs[lr2][lc2] = b_reg;
        __syncthreads();
        if (p < 15) {
            a_reg = *(const float4*)(Aptr + (p + 1) * 16);
            b_reg = *(const float4*)(Bptr + (size_t)(p + 1) * 16 * OUTD);
        }
#pragma unroll
        for (int kk = 0; kk < 16; kk++) {
            float4 a4 = *(const float4*)&As[kk][ty*4];
            float4 b4 = *(const float4*)&Bs[kk][tx*4];
            float a[4] = {a4.x, a4.y, a4.z, a4.w};
            float bb[4] = {b4.x, b4.y, b4.z, b4.w};
#pragma unroll
            for (int i = 0; i < 4; i++)
#pragma unroll
                for (int j = 0; j < 4; j++)
                    acc[i][j] = fmaf(a[i], bb[j], acc[i][j]);
        }
        __syncthreads();
    }
#pragma unroll
    for (int i = 0; i < 4; i++) {
        int rl = ty*4 + i;
#pragma unroll
        for (int j = 0; j < 4; j++) {
            int c = tx*4 + j;
            float v = __fadd_rn(acc[i][j], b2[c]);
            out[(size_t)t * (MROWS*OUTD) + (size_t)(row0 + rl) * OUTD + c] = v;
            sm_out[rl][c] = v;
        }
    }
    __syncthreads();
    // lp phase — XLA row-reduce tree: lane = term[lane]+term[lane+32], shfl.down 16..1
    int w = tid >> 5, lane = tid & 31;
    {
        const float* yrow = &y[(size_t)(t * BSZ + b) * OUTD];
        float y0 = yrow[lane], y1 = yrow[lane + 32];
        float s0y = sy[lane], s1y = sy[lane + 32];
        float logdet = g_logdet;
        for (int s = w; s < 64; s += 8) {
            float d0 = __fsub_rn(sm_out[s][lane],      y0);
            float d1 = __fsub_rn(sm_out[s][lane + 32], y1);
            float t0 = __fdiv_rn(__fmul_rn(d0, d0), s0y);
            float t1 = __fdiv_rn(__fmul_rn(d1, d1), s1y);
            float ssum = __fadd_rn(t0, t1);
#pragma unroll
            for (int off = 16; off >= 1; off >>= 1)
                ssum = __fadd_rn(ssum, __shfl_down_sync(0xffffffffu, ssum, off));
            if (lane == 0)
                lp_s[s] = __fsub_rn(__fmul_rn(-0.5f, ssum), logdet);
        }
    }
    __syncthreads();
    // log_softmax over 64 particles (XLA tree)
    if (tid < 32) {
        float v0 = lp_s[tid];
        float v1 = lp_s[tid + 32];
        float m = fmaxf(v0, v1);
#pragma unroll
        for (int off = 16; off >= 1; off >>= 1)
            m = fmaxf(m, __shfl_xor_sync(0xffffffffu, m, off));
        float sh0 = __fsub_rn(v0, m);
        float sh1 = __fsub_rn(v1, m);
        float e = __fadd_rn(expf(sh0), expf(sh1));
#pragma unroll
        for (int off = 16; off >= 1; off >>= 1)
            e = __fadd_rn(e, __shfl_down_sync(0xffffffffu, e, off));
        float ls = logf(__shfl_sync(0xffffffffu, e, 0));
        logw_s[tid]      = __fsub_rn(sh0, ls);
        logw_s[tid + 32] = __fsub_rn(sh1, ls);
    }
    __syncthreads();
    // gumbel-argmax, first-index tie-break
    uint2 gkey = g_keys[1 + 2*t + 1];
    for (int s = w; s < 64; s += 8) {
        uint32_t base = (uint32_t)s * 4096u + (uint32_t)b * 64u;
        float v0 = __fadd_rn(bits_to_gumbel(tf_bits(gkey, base + lane)),      logw_s[lane]);
        float v1 = __fadd_rn(bits_to_gumbel(tf_bits(gkey, base + 32 + lane)), logw_s[lane + 32]);
        float bv; int bi;
        if (v1 > v0) { bv = v1; bi = lane + 32; } else { bv = v0; bi = lane; }
#pragma unroll
        for (int off = 16; off >= 1; off >>= 1) {
            float ov = __shfl_xor_sync(0xffffffffu, bv, off);
            int   oi = __shfl_xor_sync(0xffffffffu, bi, off);
            if (ov > bv || (ov == bv && oi < bi)) { bv = ov; bi = oi; }
        }
        if (lane == 0) idx_s[s] = bi;
    }
    __syncthreads();
    // particle gather: x = h[resampled]
    const float4* hsrc = (const float4*)g_h;
    float4* xdst = (float4*)g_x;
    for (int e = tid; e < 64*64; e += 256) {
        int s = e >> 6, c4 = e & 63;
        xdst[(size_t)(b*64 + s) * 64 + c4] = hsrc[(size_t)(b*64 + idx_s[s]) * 64 + c4];
    }
}

extern "C" void kernel_launch(void* const* d_in, const int* in_sizes, int n_in,
                              void* d_out, int out_size) {
    (void)in_sizes; (void)n_in; (void)out_size;
    const float* u   = (const float*)d_in[0];
    const float* y   = (const float*)d_in[1];
    const float* Wih = (const float*)d_in[2];
    const float* Whh = (const float*)d_in[3];
    const float* bih = (const float*)d_in[4];
    const float* bhh = (const float*)d_in[5];
    const float* W1  = (const float*)d_in[6];
    const float* b1  = (const float*)d_in[7];
    const float* W2  = (const float*)d_in[8];
    const float* b2  = (const float*)d_in[9];
    const float* sx  = (const float*)d_in[10];
    const float* sy  = (const float*)d_in[11];
    float* out = (float*)d_out;

    k_keys<<<1, 256>>>(sy);
    k_x0<<<4096, 256>>>();
    k_uproj<<<dim3(128, 4), 256>>>(u, Wih, bih);
    for (int t = 0; t < TT; t++) {
        k_rnn<<<dim3(64, 4), 256>>>(Whh, bhh, sx, t);
        k_ffn1<<<dim3(64, 4), 256>>>(W1, b1);
        k_out_resample<<<64, 256>>>(W2, b2, y, sy, out, t);
    }
}